// round 13
// baseline (speedup 1.0000x reference)
#include <cuda_runtime.h>
#include <cuda_bf16.h>
#include <cstddef>
#include <cstdint>

#define NN 50000
#define NE 800000
#define C0 128   // in channels
#define C1 256   // hidden
#define C2 64    // latent

// ---------------- scratch (device globals; no allocation allowed) ----------------
__device__ int   g_deg[NN];
__device__ float g_dinv[NN];
__device__ int   g_is64;
__device__ int2  g_edge[NE];               // packed {src,dst}
__device__ float g_aggx[(size_t)NN * C0];
__device__ float g_h1  [(size_t)NN * C1];
__device__ float g_t2  [(size_t)NN * C2];
__device__ float g_z   [(size_t)NN * C2];
__device__ float g_dd  [(size_t)NN * C1];

// ---------------- helpers ----------------
__device__ __forceinline__ void red_add_v4(float* addr, float4 v) {
    asm volatile("red.global.add.v4.f32 [%0], {%1,%2,%3,%4};"
                 :: "l"(addr), "f"(v.x), "f"(v.y), "f"(v.z), "f"(v.w)
                 : "memory");
}

// split x into tf32 hi + tf32 lo (hi+lo reproduces x to ~2^-22)
__device__ __forceinline__ void split_tf32(float x, float& hi, float& lo) {
    uint32_t h;
    asm("cvt.rna.tf32.f32 %0, %1;" : "=r"(h) : "f"(x));
    hi = __uint_as_float(h);
    float r = x - hi;
    uint32_t l;
    asm("cvt.rna.tf32.f32 %0, %1;" : "=r"(l) : "f"(r));
    lo = __uint_as_float(l);
}

// D(4) += A(16x8 tf32, 4 regs) * B(8x8 tf32, 2 regs), fp32 accumulate
__device__ __forceinline__ void mma_tf32(float4& d, float4 a, float2 b) {
    asm volatile(
        "mma.sync.aligned.m16n8k8.row.col.f32.tf32.tf32.f32 "
        "{%0,%1,%2,%3}, {%4,%5,%6,%7}, {%8,%9}, {%0,%1,%2,%3};"
        : "+f"(d.x), "+f"(d.y), "+f"(d.z), "+f"(d.w)
        : "r"(__float_as_uint(a.x)), "r"(__float_as_uint(a.y)),
          "r"(__float_as_uint(a.z)), "r"(__float_as_uint(a.w)),
          "r"(__float_as_uint(b.x)), "r"(__float_as_uint(b.y)));
}

// ---------------- small kernels ----------------
__global__ void k_prep(const void* ei) {
    int i = blockIdx.x * blockDim.x + threadIdx.x;
    if (i < NN) g_deg[i] = 0;
    if (i == 0) {
        const long long* p = (const long long*)ei;
        int ok = 1;
        for (int q = 0; q < 64; q++) {
            long long v = p[q];
            if (v < 0 || v >= NN) { ok = 0; break; }
        }
        g_is64 = ok;
    }
}

__global__ void k_decode_count(const void* ei) {
    int t = blockIdx.x * blockDim.x + threadIdx.x;
    if (t >= NE / 4) return;
    int e = t * 4;
    int4 s4, d4;
    if (g_is64) {
        const longlong2* ps = (const longlong2*)((const long long*)ei + e);
        const longlong2* pd = (const longlong2*)((const long long*)ei + NE + e);
        longlong2 s01 = ps[0], s23 = ps[1];
        longlong2 d01 = pd[0], d23 = pd[1];
        s4 = make_int4((int)s01.x, (int)s01.y, (int)s23.x, (int)s23.y);
        d4 = make_int4((int)d01.x, (int)d01.y, (int)d23.x, (int)d23.y);
    } else {
        s4 = *(const int4*)((const int*)ei + e);
        d4 = *(const int4*)((const int*)ei + NE + e);
    }
    *(int4*)(g_edge + e)     = make_int4(s4.x, d4.x, s4.y, d4.y);
    *(int4*)(g_edge + e + 2) = make_int4(s4.z, d4.z, s4.w, d4.w);
    atomicAdd(&g_deg[d4.x], 1);
    atomicAdd(&g_deg[d4.y], 1);
    atomicAdd(&g_deg[d4.z], 1);
    atomicAdd(&g_deg[d4.w], 1);
}

// aggx[i] = dinv[i]^2 * x[i]; also materializes g_dinv (lane 0 per node).
// Consumers of g_dinv (scatters, ZOUT epilogue) launch strictly after.
__global__ void k_init_aggx(const float* __restrict__ x) {
    int t = blockIdx.x * blockDim.x + threadIdx.x;
    if (t >= NN * (C0 / 4)) return;
    int node = t / (C0 / 4);
    float dv = rsqrtf((float)g_deg[node] + 1.0f);   // +1 self loop
    if ((t & (C0 / 4 - 1)) == 0) g_dinv[node] = dv;
    float s = dv * dv;
    float4 v = ((const float4*)x)[t];
    v.x *= s; v.y *= s; v.z *= s; v.w *= s;
    ((float4*)g_aggx)[t] = v;
}

__global__ void k_scatter1(const float* __restrict__ x) {
    int gt = blockIdx.x * blockDim.x + threadIdx.x;
    int e = gt >> 5;
    int lane = gt & 31;
    if (e >= NE) return;
    int2 sd = g_edge[e];
    float norm = g_dinv[sd.x] * g_dinv[sd.y];
    float4 v = ((const float4*)x)[(size_t)sd.x * (C0 / 4) + lane];
    v.x *= norm; v.y *= norm; v.z *= norm; v.w *= norm;
    red_add_v4(g_aggx + (size_t)sd.y * C0 + lane * 4, v);
}

__global__ void k_scatter2() {
    int gt = blockIdx.x * blockDim.x + threadIdx.x;
    int e = gt >> 4;
    int lane = gt & 15;
    if (e >= NE) return;
    int2 sd = g_edge[e];
    float norm = g_dinv[sd.x] * g_dinv[sd.y];
    float4 v = ((const float4*)g_t2)[(size_t)sd.x * (C2 / 4) + lane];
    v.x *= norm; v.y *= norm; v.z *= norm; v.w *= norm;
    red_add_v4(g_z + (size_t)sd.y * C2 + lane * 4, v);
}

// ---------------- tf32x3 tensor-core GEMM ----------------
// C[M,N] = A[M,K] @ B[K,N] (+bias)(+relu)(+Z = dinv[m]^2*C + zbias).
// Block 128x64, 256 threads = 8 warps (4x2), warp tile 32x32.
// BK=8, double-buffered fragment-order smem; mma.sync m16n8k8 tf32,
// 3-pass split (AhiBhi + AhiBlo + AloBhi) for ~fp32 accuracy.
// B lane dim padded 32->33 so nt tiles land on distinct banks for staging STS.
template <int K, int RELU, int BIAS, int ZOUT>
__global__ __launch_bounds__(256, 2)
void k_gemm(const float* __restrict__ A, const float* __restrict__ B,
            const float* __restrict__ bias, float* __restrict__ C,
            int M, int Nn,
            float* __restrict__ Z = nullptr,
            const float* __restrict__ zbias = nullptr) {
    constexpr int nT = K / 8;
    __shared__ __align__(16) float Ah[2][8][32][4];
    __shared__ __align__(16) float Al[2][8][32][4];
    __shared__ __align__(16) float Bh[2][8][33][2];
    __shared__ __align__(16) float Bl[2][8][33][2];

    int tid = threadIdx.x;
    int m0 = blockIdx.x * 128, n0 = blockIdx.y * 64;
    int wid = tid >> 5, lane = tid & 31;
    int wm = wid >> 1, wn = wid & 1;       // warp grid 4(M) x 2(N)

    int a_row = tid >> 1;
    int a_h   = tid & 1;
    int a_mt  = a_row >> 4;
    int a_g   = a_row & 7;
    int a_mh  = (a_row >> 3) & 1;
    int b_kr = tid >> 4;
    int b_nc = (tid & 15) * 4;
    int b_t  = b_kr & 3;
    int b_reg = b_kr >> 2;
    int b_nt = b_nc >> 3;
    int b_g0 = b_nc & 7;

    float4 acc[2][4];
#pragma unroll
    for (int i = 0; i < 2; i++)
#pragma unroll
        for (int j = 0; j < 4; j++)
            acc[i][j] = make_float4(0.f, 0.f, 0.f, 0.f);

    float4 ra, rb;

    auto stage = [&](int buf, float4 va, float4 vb) {
        float h, l;
        float av[4] = {va.x, va.y, va.z, va.w};
#pragma unroll
        for (int j = 0; j < 4; j++) {
            int reg = (a_h << 1) | a_mh;
            int ln = a_g * 4 + j;
            split_tf32(av[j], h, l);
            Ah[buf][a_mt][ln][reg] = h;
            Al[buf][a_mt][ln][reg] = l;
        }
        if (tid < 128) {
            float bv[4] = {vb.x, vb.y, vb.z, vb.w};
#pragma unroll
            for (int j = 0; j < 4; j++) {
                int ln = (b_g0 + j) * 4 + b_t;
                split_tf32(bv[j], h, l);
                Bh[buf][b_nt][ln][b_reg] = h;
                Bl[buf][b_nt][ln][b_reg] = l;
            }
        }
    };

    auto fetch = [&](int k0, float4& va, float4& vb) {
        va = (m0 + a_row < M)
            ? *(const float4*)(A + (size_t)(m0 + a_row) * K + k0 + a_h * 4)
            : make_float4(0.f, 0.f, 0.f, 0.f);
        if (tid < 128)
            vb = *(const float4*)(B + (size_t)(k0 + b_kr) * Nn + n0 + b_nc);
    };

    fetch(0, ra, rb);
    stage(0, ra, rb);
    __syncthreads();

    int buf = 0;
#pragma unroll 1
    for (int t = 0; t < nT; t++) {
        if (t + 1 < nT) fetch((t + 1) * 8, ra, rb);

        float4 fah[2], fal[2];
        float2 fbh[4], fbl[4];
#pragma unroll
        for (int mi = 0; mi < 2; mi++) {
            fah[mi] = *(const float4*)&Ah[buf][wm * 2 + mi][lane][0];
            fal[mi] = *(const float4*)&Al[buf][wm * 2 + mi][lane][0];
        }
#pragma unroll
        for (int ni = 0; ni < 4; ni++) {
            fbh[ni] = *(const float2*)&Bh[buf][wn * 4 + ni][lane][0];
            fbl[ni] = *(const float2*)&Bl[buf][wn * 4 + ni][lane][0];
        }
        // tf32x3: hi*hi + hi*lo + lo*hi
#pragma unroll
        for (int mi = 0; mi < 2; mi++)
#pragma unroll
            for (int ni = 0; ni < 4; ni++) {
                mma_tf32(acc[mi][ni], fah[mi], fbh[ni]);
                mma_tf32(acc[mi][ni], fah[mi], fbl[ni]);
                mma_tf32(acc[mi][ni], fal[mi], fbh[ni]);
            }

        if (t + 1 < nT) {
            stage(buf ^ 1, ra, rb);
            __syncthreads();
            buf ^= 1;
        }
    }

    // ---- epilogue ----
    int g = lane >> 2, tq = lane & 3;
#pragma unroll
    for (int ni = 0; ni < 4; ni++) {
        int cb = n0 + wn * 32 + ni * 8 + 2 * tq;
        float2 bv = BIAS ? *(const float2*)(bias + cb) : make_float2(0.f, 0.f);
        float2 zbv = ZOUT ? *(const float2*)(zbias + cb) : make_float2(0.f, 0.f);
#pragma unroll
        for (int mi = 0; mi < 2; mi++) {
            int r0 = m0 + wm * 32 + mi * 16 + g;
#pragma unroll
            for (int half = 0; half < 2; half++) {
                int r = r0 + half * 8;
                if (r >= M) continue;
                float2 v;
                v.x = (half ? acc[mi][ni].z : acc[mi][ni].x) + bv.x;
                v.y = (half ? acc[mi][ni].w : acc[mi][ni].y) + bv.y;
                if (RELU) { v.x = fmaxf(v.x, 0.f); v.y = fmaxf(v.y, 0.f); }
                *(float2*)(C + (size_t)r * Nn + cb) = v;
                if (ZOUT) {
                    float dv = g_dinv[r]; float s2 = dv * dv;
                    float2 zv;
                    zv.x = v.x * s2 + zbv.x;
                    zv.y = v.y * s2 + zbv.y;
                    *(float2*)(Z + (size_t)r * Nn + cb) = zv;
                }
            }
        }
    }
}

// ---------------- launcher ----------------
extern "C" void kernel_launch(void* const* d_in, const int* in_sizes, int n_in,
                              void* d_out, int out_size) {
    const float* x   = (const float*)d_in[0];
    const void*  ei  = d_in[1];
    const float* W1  = (const float*)d_in[2];
    const float* b1  = (const float*)d_in[3];
    const float* W2  = (const float*)d_in[4];
    const float* b2  = (const float*)d_in[5];
    const float* Wd1 = (const float*)d_in[6];
    const float* bd1 = (const float*)d_in[7];
    const float* Wd2 = (const float*)d_in[8];
    const float* bd2 = (const float*)d_in[9];
    float* out = (float*)d_out;

    float *p_aggx, *p_h1, *p_t2, *p_z, *p_dd;
    cudaGetSymbolAddress((void**)&p_aggx, g_aggx);
    cudaGetSymbolAddress((void**)&p_h1,  g_h1);
    cudaGetSymbolAddress((void**)&p_t2,  g_t2);
    cudaGetSymbolAddress((void**)&p_z,   g_z);
    cudaGetSymbolAddress((void**)&p_dd,  g_dd);

    const int T = 256;
    const int MB = (NN + 127) / 128;
    k_prep<<<(NN + T - 1) / T, T>>>(ei);
    k_decode_count<<<(NE / 4 + T - 1) / T, T>>>(ei);

    // layer 1: aggregate-then-transform (A@x then @W1); init also emits g_dinv
    k_init_aggx<<<(NN * (C0 / 4) + T - 1) / T, T>>>(x);
    k_scatter1<<<(NE * 32 + T - 1) / T, T>>>(x);
    k_gemm<C0, 1, 1, 0><<<dim3(MB, C1 / 64), T>>>(p_aggx, W1, b1, p_h1, NN, C1);

    // layer 2: transform-then-aggregate; epilogue also emits z = dinv^2*t2 + b2
    k_gemm<C1, 0, 0, 1><<<dim3(MB, C2 / 64), T>>>(p_h1, W2, nullptr, p_t2,
                                                  NN, C2, p_z, b2);
    k_scatter2<<<(NE * 16 + T - 1) / T, T>>>();

    // decoder MLP
    k_gemm<C2, 1, 1, 0><<<dim3(MB, C1 / 64), T>>>(p_z, Wd1, bd1, p_dd, NN, C1);
    k_gemm<C1, 0, 1, 0><<<dim3(MB, C0 / 64), T>>>(p_dd, Wd2, bd2, out, NN, C0);
}